// round 11
// baseline (speedup 1.0000x reference)
#include <cuda_runtime.h>
#include <cstdint>

#define NS 65536
#define D  32
#define R  128

typedef unsigned long long ull;

// transposed coefficient tables: W @0, V @4096 floats, C @8192 floats, each [d][r]
__device__ float gTab[3 * D * R];
__device__ float gBias[R];

__global__ void anfis_precomp(const float* __restrict__ a,
                              const float* __restrict__ b,
                              const float* __restrict__ c) {
    int r = blockIdx.x, d = threadIdx.x;
    float av = a[r * D + d];
    float bv = fmaxf(b[r * D + d], 1e-8f);
    float w  = 0.70710678118654752f / bv;
    gTab[d * R + r]        = w;                    // W
    gTab[4096 + d * R + r] = -w * av;              // V
    gTab[8192 + d * R + r] = c[r * (D + 1) + d];   // C
    if (d == 0) gBias[r] = c[r * (D + 1) + D];
}

__device__ __forceinline__ ull fma2(ull a, ull b, ull c) {
    ull d;
    asm("fma.rn.f32x2 %0, %1, %2, %3;" : "=l"(d) : "l"(a), "l"(b), "l"(c));
    return d;
}
__device__ __forceinline__ ull add2(ull a, ull b) {
    ull d;
    asm("add.rn.f32x2 %0, %1, %2;" : "=l"(d) : "l"(a), "l"(b));
    return d;
}
__device__ __forceinline__ ull mul2(ull a, ull b) {
    ull d;
    asm("mul.rn.f32x2 %0, %1, %2;" : "=l"(d) : "l"(a), "l"(b));
    return d;
}
#define LDS128I(base, imm, lo, hi) \
    asm volatile("ld.shared.v2.u64 {%0, %1}, [%2 + %3];" \
                 : "=l"(lo), "=l"(hi) : "r"(base), "n"(imm))
__device__ __forceinline__ void sts128(uint32_t addr, ull lo, ull hi) {
    asm volatile("st.shared.v2.u64 [%0], {%1, %2};" :: "r"(addr), "l"(lo), "l"(hi));
}
__device__ __forceinline__ void unpack2(ull v, float& lo, float& hi) {
    asm("mov.b64 {%0, %1}, %2;" : "=f"(lo), "=f"(hi) : "l"(v));
}
__device__ __forceinline__ ull pack2(float lo, float hi) {
    ull v;
    asm("mov.b64 %0, {%1, %2};" : "=l"(v) : "f"(lo), "f"(hi));
    return v;
}
__device__ __forceinline__ ull shfl2(ull v, int off) {
    return __shfl_xor_sync(0xffffffffu, v, off);
}

// smem (bytes): xt[32][16] f32 @0 (2048) | pex 8 slots x 32 lanes x 64B @2048 (16384)
//               red [2][4][4 pairs][16B] @18432 (512)
#define OFF_PEX 2048
#define OFF_RED 18432
#define SMEM_FLOATS (18944 / 4)

// one d-step of this warp's 16-d slice: 4 broadcast LDS.128 + 24 fma2
#define MSTEP(k)                                                              \
    {                                                                         \
        ull w2 = pack2(cw[k], cw[k]);                                         \
        ull v2 = pack2(cv[k], cv[k]);                                         \
        ull c2 = pack2(cc[k], cc[k]);                                         \
        ull xa, xq, u;                                                        \
        LDS128I(xBo, (k) * 64 + 0, xa, xq);                                   \
        u = fma2(w2, xa, v2); agO0 = fma2(u, u, agO0); alO0 = fma2(c2, xa, alO0); \
        u = fma2(w2, xq, v2); agO1 = fma2(u, u, agO1); alO1 = fma2(c2, xq, alO1); \
        LDS128I(xBo, (k) * 64 + 16, xa, xq);                                  \
        u = fma2(w2, xa, v2); agO2 = fma2(u, u, agO2); alO2 = fma2(c2, xa, alO2); \
        u = fma2(w2, xq, v2); agO3 = fma2(u, u, agO3); alO3 = fma2(c2, xq, alO3); \
        LDS128I(xBt, (k) * 64 + 0, xa, xq);                                   \
        u = fma2(w2, xa, v2); agT0 = fma2(u, u, agT0); alT0 = fma2(c2, xa, alT0); \
        u = fma2(w2, xq, v2); agT1 = fma2(u, u, agT1); alT1 = fma2(c2, xq, alT1); \
        LDS128I(xBt, (k) * 64 + 16, xa, xq);                                  \
        u = fma2(w2, xa, v2); agT2 = fma2(u, u, agT2); alT2 = fma2(c2, xa, alT2); \
        u = fma2(w2, xq, v2); agT3 = fma2(u, u, agT3); alT3 = fma2(c2, xq, alT3); \
    }

// finalize own-half pair p: add peer partials, exp, rule-reduce, stash strengths
#define EPI(p, AG, PG, AL, PL)                                                \
    {                                                                         \
        float e0, e1;                                                         \
        unpack2(add2(AG, PG), e0, e1);                                        \
        float s0 = __expf(-e0), s1 = __expf(-e1);                             \
        ull s2 = pack2(s0, s1);                                               \
        int n = n0 + h * 8 + 2 * (p);                                         \
        strengths[n * R + r]       = s0;                                      \
        strengths[(n + 1) * R + r] = s1;                                      \
        ull pp2 = mul2(s2, add2(add2(AL, PL), bias2));                        \
        ull ss2 = s2;                                                         \
        _Pragma("unroll")                                                     \
        for (int off = 16; off > 0; off >>= 1) {                              \
            ss2 = add2(ss2, shfl2(ss2, off));                                 \
            pp2 = add2(pp2, shfl2(pp2, off));                                 \
        }                                                                     \
        if (lane == 0) sts128(redW + (p) * 16, ss2, pp2);                     \
        sv##p = s2;                                                           \
    }

#define FIN(p)                                                                \
    {                                                                         \
        ull s0q, p0q, s1q, p1q, s2q, p2q, s3q, p3q;                           \
        LDS128I(redRd, 0 * 64 + (p) * 16, s0q, p0q);                          \
        LDS128I(redRd, 1 * 64 + (p) * 16, s1q, p1q);                          \
        LDS128I(redRd, 2 * 64 + (p) * 16, s2q, p2q);                          \
        LDS128I(redRd, 3 * 64 + (p) * 16, s3q, p3q);                          \
        ull sst = add2(add2(s0q, s1q), add2(s2q, s3q));                       \
        ull ppt = add2(add2(p0q, p1q), add2(p2q, p3q));                       \
        float ta, tb_;                                                        \
        unpack2(sst, ta, tb_);                                                \
        float inva = 1.0f / (ta + 1e-8f);                                     \
        float invb = 1.0f / (tb_ + 1e-8f);                                    \
        float s0, s1;                                                         \
        unpack2(sv##p, s0, s1);                                               \
        int n = n0 + h * 8 + 2 * (p);                                         \
        normalized[n * R + r]       = s0 * inva;                              \
        normalized[(n + 1) * R + r] = s1 * invb;                              \
        if (q == 0 && lane == 0) {                                            \
            float pa, pb;                                                     \
            unpack2(ppt, pa, pb);                                             \
            pred[n]     = pa * inva;                                          \
            pred[n + 1] = pb * invb;                                          \
        }                                                                     \
    }

__global__ void __launch_bounds__(256, 2)
anfis_main(const float* __restrict__ X,
           float* __restrict__ pred,
           float* __restrict__ strengths,
           float* __restrict__ normalized) {
    __shared__ float smem[SMEM_FLOATS];
    uint32_t sbase;
    {
        uint64_t t;
        asm("cvta.to.shared.u64 %0, %1;" : "=l"(t) : "l"(smem));
        sbase = (uint32_t)t;
    }

    const int lane = threadIdx.x & 31;
    const int warp = threadIdx.x >> 5;
    const int q    = warp & 3;           // rule quarter: rules q*32+lane
    const int h    = warp >> 2;          // d-half: d in [16h, 16h+16)
    const int r    = q * 32 + lane;

    // ---- coefficients into registers (once per block, coalesced)
    float cw[16], cv[16], cc[16];
    {
        const float* tb = gTab + h * 16 * R + r;
        #pragma unroll
        for (int k = 0; k < 16; k++) {
            cw[k] = __ldg(tb + k * R);
            cv[k] = __ldg(tb + 4096 + k * R);
            cc[k] = __ldg(tb + 8192 + k * R);
        }
    }
    float biasf = __ldg(gBias + r);
    const ull bias2 = pack2(biasf, biasf);

    const uint32_t xBo  = sbase + h * 1024 + h * 32;          // own-half samples
    const uint32_t xBt  = sbase + h * 1024 + 32 - h * 32;     // other-half samples
    const uint32_t pexW = sbase + OFF_PEX + ((q * 2 + (1 - h)) * 32 + lane) * 64;
    const uint32_t pexR = sbase + OFF_PEX + ((q * 2 + h) * 32 + lane) * 64;
    const uint32_t redW = sbase + OFF_RED + (h * 4 + q) * 64;
    const uint32_t redRd = sbase + OFF_RED + h * 256;

    for (int t = blockIdx.x; t < NS / 16; t += gridDim.x) {
        const int n0 = t * 16;

        // stage x transposed: xt[d][s], 16 samples x 32 dims
        if (threadIdx.x < 128) {
            int row = threadIdx.x >> 3;   // sample 0..15
            int seg = threadIdx.x & 7;    // float4 along D
            float4 v = *reinterpret_cast<const float4*>(X + (n0 + row) * D + seg * 4);
            smem[(seg * 4 + 0) * 16 + row] = v.x;
            smem[(seg * 4 + 1) * 16 + row] = v.y;
            smem[(seg * 4 + 2) * 16 + row] = v.z;
            smem[(seg * 4 + 3) * 16 + row] = v.w;
        }
        __syncthreads();

        ull agO0 = 0, agO1 = 0, agO2 = 0, agO3 = 0;
        ull agT0 = 0, agT1 = 0, agT2 = 0, agT3 = 0;
        ull alO0 = 0, alO1 = 0, alO2 = 0, alO3 = 0;
        ull alT0 = 0, alT1 = 0, alT2 = 0, alT3 = 0;

        MSTEP(0)  MSTEP(1)  MSTEP(2)  MSTEP(3)
        MSTEP(4)  MSTEP(5)  MSTEP(6)  MSTEP(7)
        MSTEP(8)  MSTEP(9)  MSTEP(10) MSTEP(11)
        MSTEP(12) MSTEP(13) MSTEP(14) MSTEP(15)

        // hand other-half partials to peer warp
        sts128(pexW + 0,  agT0, agT1);
        sts128(pexW + 16, agT2, agT3);
        sts128(pexW + 32, alT0, alT1);
        sts128(pexW + 48, alT2, alT3);
        __syncthreads();

        ull pg0, pg1, pg2, pg3, pl0, pl1, pl2, pl3;
        LDS128I(pexR, 0,  pg0, pg1);
        LDS128I(pexR, 16, pg2, pg3);
        LDS128I(pexR, 32, pl0, pl1);
        LDS128I(pexR, 48, pl2, pl3);

        ull sv0, sv1, sv2, sv3;
        EPI(0, agO0, pg0, alO0, pl0)
        EPI(1, agO1, pg1, alO1, pl1)
        EPI(2, agO2, pg2, alO2, pl2)
        EPI(3, agO3, pg3, alO3, pl3)
        __syncthreads();

        FIN(0) FIN(1) FIN(2) FIN(3)
    }
}

extern "C" void kernel_launch(void* const* d_in, const int* in_sizes, int n_in,
                              void* d_out, int out_size) {
    const float* X = (const float*)d_in[0];
    const float* a = (const float*)d_in[1];
    const float* b = (const float*)d_in[2];
    const float* c = (const float*)d_in[3];

    float* out        = (float*)d_out;
    float* pred       = out;
    float* strengths  = out + NS;
    float* normalized = out + NS + NS * R;

    anfis_precomp<<<R, D>>>(a, b, c);
    anfis_main<<<296, 256>>>(X, pred, strengths, normalized);
}